// round 1
// baseline (speedup 1.0000x reference)
#include <cuda_runtime.h>
#include <math.h>

#define BB 256
#define SS 512
#define HH 1024
#define WW 64
#define MROWS (BB*WW)      // 16384 rows = (b, w)
#define NTILES (HH/64)     // 16 N-tiles of 64

// Scratch (no allocations allowed in kernel_launch)
__device__ float g_u[BB*HH];              // u[b,h] = hc@W1.T + b_attn   (1 MB)
__device__ float g_part[NTILES*MROWS];    // per-ntile partial scores    (1 MB)

// ---------------------------------------------------------------------------
// Kernel 1: u[b,h] = sum_k hc[b,k] * W_attn[h,k] + b_attn[h]
// Tile: 32(b) x 64(h), BK=16, 256 threads, thread tile 2x4. Grid (16, 8).
// ---------------------------------------------------------------------------
__global__ __launch_bounds__(256) void u_kernel(const float* __restrict__ hc,
                                                const float* __restrict__ Wa,
                                                const float* __restrict__ ba) {
    __shared__ float sA[16][36];   // [k][b]
    __shared__ float sB[16][68];   // [k][h]
    const int h0 = blockIdx.x * 64;
    const int b0 = blockIdx.y * 32;
    const int tid = threadIdx.x;
    const int tx = tid & 15, ty = tid >> 4;

    float acc[2][4] = {};
    for (int k0 = 0; k0 < HH; k0 += 16) {
        for (int idx = tid; idx < 32*16; idx += 256) {
            int row = idx >> 4, k = idx & 15;
            sA[k][row] = hc[(b0 + row)*HH + k0 + k];
        }
        for (int idx = tid; idx < 64*16; idx += 256) {
            int row = idx >> 4, k = idx & 15;
            sB[k][row] = Wa[(h0 + row)*(2*HH) + k0 + k];
        }
        __syncthreads();
        #pragma unroll
        for (int kk = 0; kk < 16; kk++) {
            float a0 = sA[kk][ty*2 + 0];
            float a1 = sA[kk][ty*2 + 1];
            float bq[4];
            #pragma unroll
            for (int j = 0; j < 4; j++) bq[j] = sB[kk][tx*4 + j];
            #pragma unroll
            for (int j = 0; j < 4; j++) {
                acc[0][j] = fmaf(a0, bq[j], acc[0][j]);
                acc[1][j] = fmaf(a1, bq[j], acc[1][j]);
            }
        }
        __syncthreads();
    }
    #pragma unroll
    for (int i = 0; i < 2; i++) {
        int gb = b0 + ty*2 + i;
        #pragma unroll
        for (int j = 0; j < 4; j++) {
            int gh = h0 + tx*4 + j;
            g_u[gb*HH + gh] = acc[i][j] + ba[gh];
        }
    }
}

// ---------------------------------------------------------------------------
// Kernel 2: main GEMM  E = Mt @ W2.T  fused with  s += v * tanh(E + u)
// M = 16384 gathered rows (row r -> b = r>>6, w = r&63, seq idx = len[b]-64+w)
// Tile: BM=128, BN=64, BK=16, 256 threads, thread tile 8x4.
// Writes deterministic per-ntile partial scores to g_part[nt][row].
// ---------------------------------------------------------------------------
__global__ __launch_bounds__(256) void gemm_score(const float* __restrict__ inp,
                                                  const float* __restrict__ Wa,
                                                  const float* __restrict__ v,
                                                  const int* __restrict__ slen) {
    __shared__ float sA[16][132];   // [k][m-row]
    __shared__ float sB[16][68];    // [k][n-col]
    __shared__ int rowoff[128];

    const int m0 = blockIdx.x * 128;
    const int nt = blockIdx.y;
    const int n0 = nt * 64;
    const int tid = threadIdx.x;
    const int tx = tid & 15, ty = tid >> 4;

    if (tid < 128) {
        int r = m0 + tid;
        int b = r >> 6, w = r & 63;
        rowoff[tid] = b*(SS*HH) + (slen[b] - WW + w)*HH;
    }
    __syncthreads();

    float acc[8][4] = {};
    for (int k0 = 0; k0 < HH; k0 += 16) {
        #pragma unroll
        for (int l = 0; l < 8; l++) {
            int idx = tid + l*256;
            int row = idx >> 4, k = idx & 15;
            sA[k][row] = inp[rowoff[row] + k0 + k];
        }
        #pragma unroll
        for (int l = 0; l < 4; l++) {
            int idx = tid + l*256;
            int row = idx >> 4, k = idx & 15;
            sB[k][row] = Wa[(n0 + row)*(2*HH) + HH + k0 + k];
        }
        __syncthreads();
        #pragma unroll
        for (int kk = 0; kk < 16; kk++) {
            float a[8], bq[4];
            #pragma unroll
            for (int i = 0; i < 8; i++) a[i] = sA[kk][ty*8 + i];
            #pragma unroll
            for (int j = 0; j < 4; j++) bq[j] = sB[kk][tx*4 + j];
            #pragma unroll
            for (int i = 0; i < 8; i++)
                #pragma unroll
                for (int j = 0; j < 4; j++)
                    acc[i][j] = fmaf(a[i], bq[j], acc[i][j]);
        }
        __syncthreads();
    }

    // Epilogue: s_row = sum_j v[j] * tanh(acc + u[b, j]); reduce over 16 tx lanes
    float vj[4];
    #pragma unroll
    for (int j = 0; j < 4; j++) vj[j] = v[n0 + tx*4 + j];

    #pragma unroll
    for (int i = 0; i < 8; i++) {
        int gr = m0 + ty*8 + i;
        int b = gr >> 6;
        const float* ub = &g_u[b*HH + n0 + tx*4];
        float s = 0.f;
        #pragma unroll
        for (int j = 0; j < 4; j++)
            s += vj[j] * tanhf(acc[i][j] + ub[j]);
        #pragma unroll
        for (int off = 1; off < 16; off <<= 1)
            s += __shfl_xor_sync(0xffffffffu, s, off);
        if (tx == 0) g_part[nt*MROWS + gr] = s;
    }
}

// ---------------------------------------------------------------------------
// Kernel 3: per batch — reduce partials -> softmax -> attn out -> context -> par
// Output layout: [attn (B*W) | context (B*H) | par (B*H)]
// ---------------------------------------------------------------------------
__global__ __launch_bounds__(256) void finalize(const float* __restrict__ inp,
                                                const int* __restrict__ slen,
                                                const int* __restrict__ parent,
                                                float* __restrict__ out) {
    const int b = blockIdx.x;
    const int tid = threadIdx.x;
    __shared__ float ssc[WW];
    __shared__ float sattn[WW];

    const int len = slen[b];

    if (tid < WW) {
        float s = 0.f;
        #pragma unroll
        for (int t = 0; t < NTILES; t++) s += g_part[t*MROWS + b*WW + tid];
        ssc[tid] = s;
    }
    __syncthreads();

    // Redundant (deterministic) softmax stats in every thread
    float mx = -1e30f;
    #pragma unroll 8
    for (int w = 0; w < WW; w++) mx = fmaxf(mx, ssc[w]);
    float sum = 0.f;
    #pragma unroll 8
    for (int w = 0; w < WW; w++) sum += expf(ssc[w] - mx);
    float inv = 1.f / sum;

    if (tid < WW) {
        float a = expf(ssc[tid] - mx) * inv;
        out[b*WW + tid] = a;       // attn_weights
        sattn[tid] = a;
    }
    __syncthreads();

    const float* base = inp + (size_t)b * SS * HH;
    const int off0 = (len - WW) * HH;

    // context[b,h] = sum_w attn[w] * Mt[b,w,h]
    for (int h = tid; h < HH; h += 256) {
        float acc = 0.f;
        #pragma unroll 8
        for (int w = 0; w < WW; w++)
            acc = fmaf(sattn[w], base[off0 + w*HH + h], acc);
        out[MROWS + b*HH + h] = acc;
    }

    // par[b,h] = inputs[b, len - parent - 1, h]
    const int poff = (len - parent[b] - 1) * HH;
    for (int h = tid; h < HH; h += 256)
        out[MROWS + BB*HH + b*HH + h] = base[poff + h];
}

// ---------------------------------------------------------------------------
extern "C" void kernel_launch(void* const* d_in, const int* in_sizes, int n_in,
                              void* d_out, int out_size) {
    const float* inp    = (const float*)d_in[0];   // (B,S,H)
    const float* hc     = (const float*)d_in[1];   // (B,H)
    const float* Wa     = (const float*)d_in[2];   // (H, 2H)
    const float* ba     = (const float*)d_in[3];   // (H,)
    const float* v      = (const float*)d_in[4];   // (H,)
    const int*   slen   = (const int*)d_in[5];     // (B,)
    const int*   parent = (const int*)d_in[6];     // (B,)
    float* out = (float*)d_out;

    u_kernel<<<dim3(HH/64, BB/32), 256>>>(hc, Wa, ba);
    gemm_score<<<dim3(MROWS/128, NTILES), 256>>>(inp, Wa, v, slen);
    finalize<<<BB, 256>>>(inp, slen, parent, out);
}

// round 3
// speedup vs baseline: 3.1553x; 3.1553x over previous
#include <cuda_runtime.h>
#include <cuda_bf16.h>
#include <math.h>
#include <stdint.h>

#define BB 256
#define SS 512
#define HH 1024
#define WW 64
#define MROWS (BB*WW)        // 16384 score rows
#define AROWS (MROWS + BB)   // + 256 hc rows
#define NT 8                 // N tiles of 128
#define BM 128
#define BN 128
#define BK 32                // bf16 K per stage
#define KITERS (HH/BK)       // 32
#define RSTRIDE 80           // 40 bf16 padded row (conflict-free ldmatrix)
#define SPLIT_BYTES (BM*RSTRIDE)       // 10240
#define B_OFF (2*SPLIT_BYTES)          // 20480
#define STAGE_BYTES (4*SPLIT_BYTES)    // 40960
#define SMEM_ALLOC (2*STAGE_BYTES)     // 81920

// ---------------- scratch ----------------
__device__ __nv_bfloat16 g_A0[(size_t)AROWS*HH];
__device__ __nv_bfloat16 g_A1[(size_t)AROWS*HH];
__device__ __nv_bfloat16 g_W0[(size_t)HH*2*HH];
__device__ __nv_bfloat16 g_W1[(size_t)HH*2*HH];
__device__ float g_u[(size_t)BB*HH];
__device__ float g_part[NT*MROWS];

// ---------------- PTX helpers (no sm_103a-gated features) ----------------
__device__ __forceinline__ uint32_t smem_u32(const void* p) {
    uint32_t a;
    asm("{ .reg .u64 t; cvta.to.shared.u64 t, %1; cvt.u32.u64 %0, t; }" : "=r"(a) : "l"(p));
    return a;
}
__device__ __forceinline__ void cpasync16(uint32_t dst, const void* src) {
    asm volatile("cp.async.cg.shared.global [%0], [%1], 16;" :: "r"(dst), "l"(src) : "memory");
}
__device__ __forceinline__ void cp_commit() { asm volatile("cp.async.commit_group;" ::: "memory"); }
template <int N> __device__ __forceinline__ void cp_wait() {
    asm volatile("cp.async.wait_group %0;" :: "n"(N) : "memory");
}
#define LDSM(r0,r1,r2,r3,addr) \
    asm volatile("ldmatrix.sync.aligned.m8n8.x4.shared.b16 {%0,%1,%2,%3}, [%4];" \
        : "=r"(r0),"=r"(r1),"=r"(r2),"=r"(r3) : "r"(addr))
#define MMA(d, a, b) \
    asm volatile("mma.sync.aligned.m16n8k16.row.col.f32.bf16.bf16.f32 " \
        "{%0,%1,%2,%3},{%4,%5,%6,%7},{%8,%9},{%0,%1,%2,%3};" \
        : "+f"((d)[0]),"+f"((d)[1]),"+f"((d)[2]),"+f"((d)[3]) \
        : "r"((a)[0]),"r"((a)[1]),"r"((a)[2]),"r"((a)[3]),"r"((b)[0]),"r"((b)[1]))

// ---------------- split helpers ----------------
__device__ __forceinline__ void split2(float x, __nv_bfloat16& a0, __nv_bfloat16& a1) {
    a0 = __float2bfloat16_rn(x);
    a1 = __float2bfloat16_rn(x - __bfloat162float(a0));
}

// ---------------- kernel: split W into 2 bf16 planes ----------------
__global__ __launch_bounds__(256) void split_w(const float* __restrict__ Wa) {
    size_t base = ((size_t)blockIdx.x * 256 + threadIdx.x) * 4;
    float4 x = *reinterpret_cast<const float4*>(Wa + base);
    float v4[4] = {x.x, x.y, x.z, x.w};
    __nv_bfloat16 s0[4], s1[4];
    #pragma unroll
    for (int i = 0; i < 4; i++) split2(v4[i], s0[i], s1[i]);
    #pragma unroll
    for (int i = 0; i < 2; i++) {
        reinterpret_cast<__nv_bfloat162*>(g_W0 + base)[i] = __nv_bfloat162(s0[2*i], s0[2*i+1]);
        reinterpret_cast<__nv_bfloat162*>(g_W1 + base)[i] = __nv_bfloat162(s1[2*i], s1[2*i+1]);
    }
}

// ---------------- kernel: gather rows + split ----------------
__global__ __launch_bounds__(256) void gather_split_a(const float* __restrict__ inp,
                                                      const float* __restrict__ hc,
                                                      const int* __restrict__ slen) {
    int row = blockIdx.x;
    const float* src;
    if (row < MROWS) {
        int b = row >> 6, w = row & 63;
        src = inp + ((size_t)b * SS + (slen[b] - WW + w)) * HH;
    } else {
        src = hc + (size_t)(row - MROWS) * HH;
    }
    int i = threadIdx.x * 4;
    float4 x = *reinterpret_cast<const float4*>(src + i);
    float v4[4] = {x.x, x.y, x.z, x.w};
    __nv_bfloat16 s0[4], s1[4];
    #pragma unroll
    for (int k = 0; k < 4; k++) split2(v4[k], s0[k], s1[k]);
    size_t base = (size_t)row * HH + i;
    #pragma unroll
    for (int k = 0; k < 2; k++) {
        reinterpret_cast<__nv_bfloat162*>(g_A0 + base)[k] = __nv_bfloat162(s0[2*k], s0[2*k+1]);
        reinterpret_cast<__nv_bfloat162*>(g_A1 + base)[k] = __nv_bfloat162(s1[2*k], s1[2*k+1]);
    }
}

// ---------------- HMMA GEMM: emulated fp32 via 4 bf16 products ----------------
// mode 0: rows = hc (arow_base=MROWS), kofs=0  -> g_u = D + b_attn
// mode 1: rows = Mt gather (arow_base=0), kofs=HH -> g_part[nt][row] = sum_n v*tanh(D+u)
__global__ __launch_bounds__(256, 1) void gemm_hmma(int mode, int arow_base, int kofs,
                                                    const float* __restrict__ vv,
                                                    const float* __restrict__ ba) {
    extern __shared__ __align__(128) char smem_raw[];
    const uint32_t sbase = smem_u32(smem_raw);
    __shared__ float srow[2][BM];

    const int tid = threadIdx.x;
    const int lane = tid & 31;
    const int wid = tid >> 5;
    const int wm = (wid & 3) * 32;     // warp M offset
    const int wn = (wid >> 2) * 64;    // warp N offset
    const int n0 = blockIdx.x * BN;    // x = n-tile (fastest -> A reuse in L2)
    const int m0 = blockIdx.y * BM;

    const __nv_bfloat16* gA[2] = {g_A0, g_A1};
    const __nv_bfloat16* gW[2] = {g_W0, g_W1};

    auto fill = [&](int s, int k0) {
        uint32_t stg = sbase + s * STAGE_BYTES;
        #pragma unroll
        for (int j = 0; j < 4; j++) {        // A: 2 splits x 128 rows x 4 chunks
            int c = tid + j * 256;
            int p = c >> 9, idx = c & 511, row = idx >> 2, ch = idx & 3;
            cpasync16(stg + p * SPLIT_BYTES + row * RSTRIDE + ch * 16,
                      gA[p] + (size_t)(arow_base + m0 + row) * HH + k0 + ch * 8);
        }
        #pragma unroll
        for (int j = 0; j < 4; j++) {        // B: 2 splits x 128 rows x 4 chunks
            int c = tid + j * 256;
            int p = c >> 9, idx = c & 511, row = idx >> 2, ch = idx & 3;
            cpasync16(stg + B_OFF + p * SPLIT_BYTES + row * RSTRIDE + ch * 16,
                      gW[p] + (size_t)(n0 + row) * (2 * HH) + kofs + k0 + ch * 8);
        }
    };

    float acc[2][8][4] = {};
    const uint32_t lrow = lane & 15;
    const uint32_t lkb = (lane >> 4) * 16;

    fill(0, 0);
    cp_commit();

    for (int it = 0; it < KITERS; ++it) {
        if (it + 1 < KITERS) {
            fill((it + 1) & 1, (it + 1) * BK);
            cp_commit();
            cp_wait<1>();
        } else {
            cp_wait<0>();
        }
        __syncthreads();

        uint32_t stg = sbase + (it & 1) * STAGE_BYTES;
        uint32_t aB = stg + (wm + lrow) * RSTRIDE + lkb;
        uint32_t bB = stg + B_OFF + (wn + lrow) * RSTRIDE + lkb;

        #pragma unroll
        for (int ks = 0; ks < 2; ks++) {
            #pragma unroll
            for (int pb = 0; pb < 2; pb++) {
                uint32_t bf[8][2];
                #pragma unroll
                for (int n2 = 0; n2 < 4; n2++) {
                    uint32_t t0, t1, t2, t3;
                    LDSM(t0, t1, t2, t3, bB + pb * SPLIT_BYTES + ks * 32 + n2 * 16 * RSTRIDE);
                    bf[2*n2][0] = t0; bf[2*n2][1] = t2;
                    bf[2*n2+1][0] = t1; bf[2*n2+1][1] = t3;
                }
                #pragma unroll
                for (int pa = 0; pa < 2; pa++) {
                    uint32_t af[2][4];
                    #pragma unroll
                    for (int mi = 0; mi < 2; mi++)
                        LDSM(af[mi][0], af[mi][1], af[mi][2], af[mi][3],
                             aB + pa * SPLIT_BYTES + ks * 32 + mi * 16 * RSTRIDE);
                    #pragma unroll
                    for (int mi = 0; mi < 2; mi++)
                        #pragma unroll
                        for (int ni = 0; ni < 8; ni++)
                            MMA(acc[mi][ni], af[mi], bf[ni]);
                }
            }
        }
        __syncthreads();
    }

    const int quad = lane >> 2, qt = lane & 3;

    if (mode == 1) {
        // epilogue: s_row = sum_n v[n]*tanh(E + u[b,n]); per-warp rows all in one batch
        const int b_warp = (m0 + wm) >> 6;
        const float* up = g_u + (size_t)b_warp * HH + n0 + wn;
        const float* vp = vv + n0 + wn;
        float rs[4] = {0.f, 0.f, 0.f, 0.f};
        #pragma unroll
        for (int mi = 0; mi < 2; mi++)
            #pragma unroll
            for (int ni = 0; ni < 8; ni++)
                #pragma unroll
                for (int r = 0; r < 4; r++) {
                    int col = ni * 8 + qt * 2 + (r & 1);
                    float e = acc[mi][ni][r] + __ldg(up + col);
                    rs[mi * 2 + (r >> 1)] += __ldg(vp + col) * tanhf(e);
                }
        #pragma unroll
        for (int i = 0; i < 4; i++) {
            rs[i] += __shfl_xor_sync(0xffffffffu, rs[i], 1);
            rs[i] += __shfl_xor_sync(0xffffffffu, rs[i], 2);
        }
        if (qt == 0) {
            #pragma unroll
            for (int mi = 0; mi < 2; mi++)
                #pragma unroll
                for (int hf = 0; hf < 2; hf++)
                    srow[wid >> 2][wm + mi * 16 + hf * 8 + quad] = rs[mi * 2 + hf];
        }
        __syncthreads();
        if (tid < BM)
            g_part[blockIdx.x * MROWS + m0 + tid] = srow[0][tid] + srow[1][tid];
    } else {
        // u = D + b_attn
        #pragma unroll
        for (int mi = 0; mi < 2; mi++)
            #pragma unroll
            for (int ni = 0; ni < 8; ni++)
                #pragma unroll
                for (int r = 0; r < 4; r++) {
                    int row = m0 + wm + mi * 16 + (r >> 1) * 8 + quad;
                    int col = n0 + wn + ni * 8 + qt * 2 + (r & 1);
                    g_u[(size_t)row * HH + col] = acc[mi][ni][r] + __ldg(ba + col);
                }
    }
}

// ---------------- finalize: softmax + context + parent ----------------
__global__ __launch_bounds__(256) void finalize(const float* __restrict__ inp,
                                                const int* __restrict__ slen,
                                                const int* __restrict__ parent,
                                                float* __restrict__ out) {
    const int b = blockIdx.x;
    const int tid = threadIdx.x;
    __shared__ float ssc[WW];
    __shared__ float sattn[WW];
    const int len = slen[b];

    if (tid < WW) {
        float s = 0.f;
        #pragma unroll
        for (int t = 0; t < NT; t++) s += g_part[t * MROWS + b * WW + tid];
        ssc[tid] = s;
    }
    __syncthreads();

    float mx = -1e30f;
    #pragma unroll 8
    for (int w = 0; w < WW; w++) mx = fmaxf(mx, ssc[w]);
    float sum = 0.f;
    #pragma unroll 8
    for (int w = 0; w < WW; w++) sum += expf(ssc[w] - mx);
    float inv = 1.f / sum;

    if (tid < WW) {
        float a = expf(ssc[tid] - mx) * inv;
        out[b * WW + tid] = a;
        sattn[tid] = a;
    }
    __syncthreads();

    const float* base = inp + (size_t)b * SS * HH;
    const int off0 = (len - WW) * HH;
    for (int h = tid; h < HH; h += 256) {
        float acc = 0.f;
        #pragma unroll 8
        for (int w = 0; w < WW; w++)
            acc = fmaf(sattn[w], base[off0 + w * HH + h], acc);
        out[MROWS + b * HH + h] = acc;
    }
    const int poff = (len - parent[b] - 1) * HH;
    for (int h = tid; h < HH; h += 256)
        out[MROWS + BB * HH + b * HH + h] = base[poff + h];
}

// ---------------------------------------------------------------------------
extern "C" void kernel_launch(void* const* d_in, const int* in_sizes, int n_in,
                              void* d_out, int out_size) {
    const float* inp    = (const float*)d_in[0];
    const float* hc     = (const float*)d_in[1];
    const float* Wa     = (const float*)d_in[2];
    const float* ba     = (const float*)d_in[3];
    const float* v      = (const float*)d_in[4];
    const int*   slen   = (const int*)d_in[5];
    const int*   parent = (const int*)d_in[6];
    float* out = (float*)d_out;

    static int configured = 0;
    if (!configured) {
        cudaFuncSetAttribute(gemm_hmma, cudaFuncAttributeMaxDynamicSharedMemorySize, SMEM_ALLOC);
        configured = 1;
    }

    split_w<<<(HH * 2 * HH) / 1024, 256>>>(Wa);
    gather_split_a<<<AROWS, 256>>>(inp, hc, slen);
    gemm_hmma<<<dim3(NT, BB / BM), 256, SMEM_ALLOC>>>(0, MROWS, 0, v, ba);   // u
    gemm_hmma<<<dim3(NT, MROWS / BM), 256, SMEM_ALLOC>>>(1, 0, HH, v, ba);   // scores
    finalize<<<BB, 256>>>(inp, slen, parent, out);
}

// round 4
// speedup vs baseline: 4.0500x; 1.2836x over previous
#include <cuda_runtime.h>
#include <cuda_bf16.h>
#include <math.h>
#include <stdint.h>

#define BB 256
#define SS 512
#define HH 1024
#define WW 64
#define MROWS (BB*WW)        // 16384 score rows
#define AROWS (MROWS + BB)   // + 256 hc rows
#define NT 8                 // N tiles of 128
#define BM 128
#define BN 128
#define BK 32                // bf16 K per stage
#define KITERS (HH/BK)       // 32
#define RSTRIDE 80           // 40 bf16 padded row (conflict-free ldmatrix)
#define SPLIT_BYTES (BM*RSTRIDE)       // 10240
#define B_OFF (2*SPLIT_BYTES)          // 20480
#define STAGE_BYTES (4*SPLIT_BYTES)    // 40960
#define SMEM_ALLOC (2*STAGE_BYTES)     // 81920

// ---------------- scratch ----------------
__device__ __nv_bfloat16 g_A0[(size_t)AROWS*HH];
__device__ __nv_bfloat16 g_A1[(size_t)AROWS*HH];
__device__ __nv_bfloat16 g_W0[(size_t)HH*2*HH];
__device__ __nv_bfloat16 g_W1[(size_t)HH*2*HH];
__device__ float g_u[(size_t)BB*HH];
__device__ float g_part[NT*MROWS];

// ---------------- PTX helpers (no sm_103a-gated features) ----------------
__device__ __forceinline__ uint32_t smem_u32(const void* p) {
    uint32_t a;
    asm("{ .reg .u64 t; cvta.to.shared.u64 t, %1; cvt.u32.u64 %0, t; }" : "=r"(a) : "l"(p));
    return a;
}
__device__ __forceinline__ void cpasync16(uint32_t dst, const void* src) {
    asm volatile("cp.async.cg.shared.global [%0], [%1], 16;" :: "r"(dst), "l"(src) : "memory");
}
__device__ __forceinline__ void cp_commit() { asm volatile("cp.async.commit_group;" ::: "memory"); }
template <int N> __device__ __forceinline__ void cp_wait() {
    asm volatile("cp.async.wait_group %0;" :: "n"(N) : "memory");
}
#define LDSM(r0,r1,r2,r3,addr) \
    asm volatile("ldmatrix.sync.aligned.m8n8.x4.shared.b16 {%0,%1,%2,%3}, [%4];" \
        : "=r"(r0),"=r"(r1),"=r"(r2),"=r"(r3) : "r"(addr))
#define MMA(d, a, b) \
    asm volatile("mma.sync.aligned.m16n8k16.row.col.f32.bf16.bf16.f32 " \
        "{%0,%1,%2,%3},{%4,%5,%6,%7},{%8,%9},{%0,%1,%2,%3};" \
        : "+f"((d)[0]),"+f"((d)[1]),"+f"((d)[2]),"+f"((d)[3]) \
        : "r"((a)[0]),"r"((a)[1]),"r"((a)[2]),"r"((a)[3]),"r"((b)[0]),"r"((b)[1]))

// ---------------- split helpers ----------------
__device__ __forceinline__ void split2(float x, __nv_bfloat16& a0, __nv_bfloat16& a1) {
    a0 = __float2bfloat16_rn(x);
    a1 = __float2bfloat16_rn(x - __bfloat162float(a0));
}

// ---------------- kernel: split W into 2 bf16 planes ----------------
__global__ __launch_bounds__(256) void split_w(const float* __restrict__ Wa) {
    size_t base = ((size_t)blockIdx.x * 256 + threadIdx.x) * 4;
    float4 x = *reinterpret_cast<const float4*>(Wa + base);
    float v4[4] = {x.x, x.y, x.z, x.w};
    __nv_bfloat16 s0[4], s1[4];
    #pragma unroll
    for (int i = 0; i < 4; i++) split2(v4[i], s0[i], s1[i]);
    #pragma unroll
    for (int i = 0; i < 2; i++) {
        reinterpret_cast<__nv_bfloat162*>(g_W0 + base)[i] = __nv_bfloat162(s0[2*i], s0[2*i+1]);
        reinterpret_cast<__nv_bfloat162*>(g_W1 + base)[i] = __nv_bfloat162(s1[2*i], s1[2*i+1]);
    }
}

// ---------------- kernel: gather rows + split ----------------
__global__ __launch_bounds__(256) void gather_split_a(const float* __restrict__ inp,
                                                      const float* __restrict__ hc,
                                                      const int* __restrict__ slen) {
    int row = blockIdx.x;
    const float* src;
    if (row < MROWS) {
        int b = row >> 6, w = row & 63;
        src = inp + ((size_t)b * SS + (slen[b] - WW + w)) * HH;
    } else {
        src = hc + (size_t)(row - MROWS) * HH;
    }
    int i = threadIdx.x * 4;
    float4 x = *reinterpret_cast<const float4*>(src + i);
    float v4[4] = {x.x, x.y, x.z, x.w};
    __nv_bfloat16 s0[4], s1[4];
    #pragma unroll
    for (int k = 0; k < 4; k++) split2(v4[k], s0[k], s1[k]);
    size_t base = (size_t)row * HH + i;
    #pragma unroll
    for (int k = 0; k < 2; k++) {
        reinterpret_cast<__nv_bfloat162*>(g_A0 + base)[k] = __nv_bfloat162(s0[2*k], s0[2*k+1]);
        reinterpret_cast<__nv_bfloat162*>(g_A1 + base)[k] = __nv_bfloat162(s1[2*k], s1[2*k+1]);
    }
}

// ---------------- HMMA GEMM: emulated fp32 via 3 bf16 products ----------------
// (a0+a1)(b0+b1) ~= a0b0 + a0b1 + a1b0  (a1b1 ~ 2^-18 rel, dropped)
// mode 0: rows = hc (arow_base=MROWS), kofs=0  -> g_u = D + b_attn
// mode 1: rows = Mt gather (arow_base=0), kofs=HH -> g_part[nt][row] = sum_n v*tanh(D+u)
__global__ __launch_bounds__(256, 2) void gemm_hmma(int mode, int arow_base, int kofs,
                                                    const float* __restrict__ vv,
                                                    const float* __restrict__ ba) {
    extern __shared__ __align__(128) char smem_raw[];
    const uint32_t sbase = smem_u32(smem_raw);
    __shared__ float srow[2][BM];

    const int tid = threadIdx.x;
    const int lane = tid & 31;
    const int wid = tid >> 5;
    const int wm = (wid & 3) * 32;     // warp M offset
    const int wn = (wid >> 2) * 64;    // warp N offset
    const int n0 = blockIdx.x * BN;    // x = n-tile (A reuse in L2)
    const int m0 = blockIdx.y * BM;

    // ---- precomputed fill pointers (only +k0 varies per iter) ----
    const int rowq = tid >> 2, ch = tid & 3;
    const __nv_bfloat16* srcA[4];
    const __nv_bfloat16* srcB[4];
    uint32_t dofA[4], dofB[4];
    {
        size_t ra0 = (size_t)(arow_base + m0 + rowq) * HH + ch * 8;
        size_t ra1 = (size_t)(arow_base + m0 + 64 + rowq) * HH + ch * 8;
        srcA[0] = g_A0 + ra0;  srcA[1] = g_A0 + ra1;
        srcA[2] = g_A1 + ra0;  srcA[3] = g_A1 + ra1;
        dofA[0] = rowq * RSTRIDE + ch * 16;
        dofA[1] = (64 + rowq) * RSTRIDE + ch * 16;
        dofA[2] = SPLIT_BYTES + dofA[0];
        dofA[3] = SPLIT_BYTES + dofA[1];
        size_t rb0 = (size_t)(n0 + rowq) * (2 * HH) + kofs + ch * 8;
        size_t rb1 = (size_t)(n0 + 64 + rowq) * (2 * HH) + kofs + ch * 8;
        srcB[0] = g_W0 + rb0;  srcB[1] = g_W0 + rb1;
        srcB[2] = g_W1 + rb0;  srcB[3] = g_W1 + rb1;
        dofB[0] = B_OFF + rowq * RSTRIDE + ch * 16;
        dofB[1] = B_OFF + (64 + rowq) * RSTRIDE + ch * 16;
        dofB[2] = SPLIT_BYTES + dofB[0];
        dofB[3] = SPLIT_BYTES + dofB[1];
    }

    auto fill = [&](int s, int k0) {
        uint32_t stg = sbase + s * STAGE_BYTES;
        #pragma unroll
        for (int j = 0; j < 4; j++) cpasync16(stg + dofA[j], srcA[j] + k0);
        #pragma unroll
        for (int j = 0; j < 4; j++) cpasync16(stg + dofB[j], srcB[j] + k0);
    };

    float acc[2][8][4] = {};
    const uint32_t lrow = lane & 15;
    const uint32_t lkb = (lane >> 4) * 16;

    fill(0, 0);
    cp_commit();

    for (int it = 0; it < KITERS; ++it) {
        if (it + 1 < KITERS) {
            fill((it + 1) & 1, (it + 1) * BK);
            cp_commit();
            cp_wait<1>();
        } else {
            cp_wait<0>();
        }
        __syncthreads();

        uint32_t stg = sbase + (it & 1) * STAGE_BYTES;
        uint32_t aAddr = stg + (wm + lrow) * RSTRIDE + lkb;
        uint32_t bAddr = stg + B_OFF + (wn + lrow) * RSTRIDE + lkb;

        #pragma unroll
        for (int ks = 0; ks < 2; ks++) {
            uint32_t a0f[2][4], a1f[2][4];
            #pragma unroll
            for (int mi = 0; mi < 2; mi++)
                LDSM(a0f[mi][0], a0f[mi][1], a0f[mi][2], a0f[mi][3],
                     aAddr + ks * 32 + mi * 16 * RSTRIDE);
            #pragma unroll
            for (int mi = 0; mi < 2; mi++)
                LDSM(a1f[mi][0], a1f[mi][1], a1f[mi][2], a1f[mi][3],
                     aAddr + SPLIT_BYTES + ks * 32 + mi * 16 * RSTRIDE);
            #pragma unroll
            for (int n2 = 0; n2 < 4; n2++) {
                uint32_t t0, t1, t2, t3;
                LDSM(t0, t1, t2, t3, bAddr + ks * 32 + n2 * 16 * RSTRIDE);
                {
                    uint32_t be[2] = {t0, t2}, bo[2] = {t1, t3};
                    #pragma unroll
                    for (int mi = 0; mi < 2; mi++) {
                        MMA(acc[mi][2*n2],   a0f[mi], be);
                        MMA(acc[mi][2*n2+1], a0f[mi], bo);
                        MMA(acc[mi][2*n2],   a1f[mi], be);
                        MMA(acc[mi][2*n2+1], a1f[mi], bo);
                    }
                }
                LDSM(t0, t1, t2, t3, bAddr + SPLIT_BYTES + ks * 32 + n2 * 16 * RSTRIDE);
                {
                    uint32_t be[2] = {t0, t2}, bo[2] = {t1, t3};
                    #pragma unroll
                    for (int mi = 0; mi < 2; mi++) {
                        MMA(acc[mi][2*n2],   a0f[mi], be);
                        MMA(acc[mi][2*n2+1], a0f[mi], bo);
                    }
                }
            }
        }
        __syncthreads();
    }

    const int quad = lane >> 2, qt = lane & 3;

    if (mode == 1) {
        // epilogue: s_row = sum_n v[n]*tanh(E + u[b,n]); per-warp rows all in one batch
        const int b_warp = (m0 + wm) >> 6;
        const float* up = g_u + (size_t)b_warp * HH + n0 + wn;
        const float* vp = vv + n0 + wn;
        float rs[4] = {0.f, 0.f, 0.f, 0.f};
        #pragma unroll
        for (int mi = 0; mi < 2; mi++)
            #pragma unroll
            for (int ni = 0; ni < 8; ni++)
                #pragma unroll
                for (int r = 0; r < 4; r++) {
                    int col = ni * 8 + qt * 2 + (r & 1);
                    float e = acc[mi][ni][r] + __ldg(up + col);
                    rs[mi * 2 + (r >> 1)] += __ldg(vp + col) * tanhf(e);
                }
        #pragma unroll
        for (int i = 0; i < 4; i++) {
            rs[i] += __shfl_xor_sync(0xffffffffu, rs[i], 1);
            rs[i] += __shfl_xor_sync(0xffffffffu, rs[i], 2);
        }
        if (qt == 0) {
            #pragma unroll
            for (int mi = 0; mi < 2; mi++)
                #pragma unroll
                for (int hf = 0; hf < 2; hf++)
                    srow[wid >> 2][wm + mi * 16 + hf * 8 + quad] = rs[mi * 2 + hf];
        }
        __syncthreads();
        if (tid < BM)
            g_part[blockIdx.x * MROWS + m0 + tid] = srow[0][tid] + srow[1][tid];
    } else {
        // u = D + b_attn
        #pragma unroll
        for (int mi = 0; mi < 2; mi++)
            #pragma unroll
            for (int ni = 0; ni < 8; ni++)
                #pragma unroll
                for (int r = 0; r < 4; r++) {
                    int row = m0 + wm + mi * 16 + (r >> 1) * 8 + quad;
                    int col = n0 + wn + ni * 8 + qt * 2 + (r & 1);
                    g_u[(size_t)row * HH + col] = acc[mi][ni][r] + __ldg(ba + col);
                }
    }
}

// ---------------- finalize: softmax + context + parent ----------------
__global__ __launch_bounds__(256) void finalize(const float* __restrict__ inp,
                                                const int* __restrict__ slen,
                                                const int* __restrict__ parent,
                                                float* __restrict__ out) {
    const int b = blockIdx.x;
    const int tid = threadIdx.x;
    __shared__ float ssc[WW];
    __shared__ float sattn[WW];
    const int len = slen[b];

    if (tid < WW) {
        float s = 0.f;
        #pragma unroll
        for (int t = 0; t < NT; t++) s += g_part[t * MROWS + b * WW + tid];
        ssc[tid] = s;
    }
    __syncthreads();

    float mx = -1e30f;
    #pragma unroll 8
    for (int w = 0; w < WW; w++) mx = fmaxf(mx, ssc[w]);
    float sum = 0.f;
    #pragma unroll 8
    for (int w = 0; w < WW; w++) sum += expf(ssc[w] - mx);
    float inv = 1.f / sum;

    if (tid < WW) {
        float a = expf(ssc[tid] - mx) * inv;
        out[b * WW + tid] = a;
        sattn[tid] = a;
    }
    __syncthreads();

    const float* base = inp + (size_t)b * SS * HH;
    const int off0 = (len - WW) * HH;
    for (int h = tid; h < HH; h += 256) {
        float acc = 0.f;
        #pragma unroll 8
        for (int w = 0; w < WW; w++)
            acc = fmaf(sattn[w], base[off0 + w * HH + h], acc);
        out[MROWS + b * HH + h] = acc;
    }
    const int poff = (len - parent[b] - 1) * HH;
    for (int h = tid; h < HH; h += 256)
        out[MROWS + BB * HH + b * HH + h] = base[poff + h];
}

// ---------------------------------------------------------------------------
extern "C" void kernel_launch(void* const* d_in, const int* in_sizes, int n_in,
                              void* d_out, int out_size) {
    const float* inp    = (const float*)d_in[0];
    const float* hc     = (const float*)d_in[1];
    const float* Wa     = (const float*)d_in[2];
    const float* ba     = (const float*)d_in[3];
    const float* v      = (const float*)d_in[4];
    const int*   slen   = (const int*)d_in[5];
    const int*   parent = (const int*)d_in[6];
    float* out = (float*)d_out;

    static int configured = 0;
    if (!configured) {
        cudaFuncSetAttribute(gemm_hmma, cudaFuncAttributeMaxDynamicSharedMemorySize, SMEM_ALLOC);
        configured = 1;
    }

    split_w<<<(HH * 2 * HH) / 1024, 256>>>(Wa);
    gather_split_a<<<AROWS, 256>>>(inp, hc, slen);
    gemm_hmma<<<dim3(NT, BB / BM), 256, SMEM_ALLOC>>>(0, MROWS, 0, v, ba);   // u
    gemm_hmma<<<dim3(NT, MROWS / BM), 256, SMEM_ALLOC>>>(1, 0, HH, v, ba);   // scores
    finalize<<<BB, 256>>>(inp, slen, parent, out);
}

// round 5
// speedup vs baseline: 4.2443x; 1.0480x over previous
#include <cuda_runtime.h>
#include <cuda_bf16.h>
#include <math.h>
#include <stdint.h>

#define BB 256
#define SS 512
#define HH 1024
#define WW 64
#define MROWS (BB*WW)        // 16384 score rows
#define AROWS (MROWS + BB)   // + 256 hc rows
#define NT 8                 // N tiles of 128
#define BM 128
#define BN 128
#define BK 32                // bf16 K per stage
#define KITERS (HH/BK)       // 32
#define RSTRIDE 80           // 40 bf16 padded row (conflict-free ldmatrix)
#define SPLIT_BYTES (BM*RSTRIDE)       // 10240
#define B_OFF (2*SPLIT_BYTES)          // 20480
#define STAGE_BYTES (4*SPLIT_BYTES)    // 40960
#define SMEM_ALLOC (2*STAGE_BYTES)     // 81920

// ---------------- scratch ----------------
__device__ __nv_bfloat16 g_A0[(size_t)AROWS*HH];
__device__ __nv_bfloat16 g_A1[(size_t)AROWS*HH];
__device__ __nv_bfloat16 g_W0[(size_t)HH*2*HH];
__device__ __nv_bfloat16 g_W1[(size_t)HH*2*HH];
__device__ float g_u[(size_t)BB*HH];
__device__ float g_part[NT*MROWS];

// ---------------- PTX helpers (no sm_103a-gated features) ----------------
__device__ __forceinline__ uint32_t smem_u32(const void* p) {
    uint32_t a;
    asm("{ .reg .u64 t; cvta.to.shared.u64 t, %1; cvt.u32.u64 %0, t; }" : "=r"(a) : "l"(p));
    return a;
}
__device__ __forceinline__ void cpasync16(uint32_t dst, const void* src) {
    asm volatile("cp.async.cg.shared.global [%0], [%1], 16;" :: "r"(dst), "l"(src) : "memory");
}
__device__ __forceinline__ void cp_commit() { asm volatile("cp.async.commit_group;" ::: "memory"); }
template <int N> __device__ __forceinline__ void cp_wait() {
    asm volatile("cp.async.wait_group %0;" :: "n"(N) : "memory");
}
#define LDSM(r0,r1,r2,r3,addr) \
    asm volatile("ldmatrix.sync.aligned.m8n8.x4.shared.b16 {%0,%1,%2,%3}, [%4];" \
        : "=r"(r0),"=r"(r1),"=r"(r2),"=r"(r3) : "r"(addr))
#define MMA(d, a, b) \
    asm volatile("mma.sync.aligned.m16n8k16.row.col.f32.bf16.bf16.f32 " \
        "{%0,%1,%2,%3},{%4,%5,%6,%7},{%8,%9},{%0,%1,%2,%3};" \
        : "+f"((d)[0]),"+f"((d)[1]),"+f"((d)[2]),"+f"((d)[3]) \
        : "r"((a)[0]),"r"((a)[1]),"r"((a)[2]),"r"((a)[3]),"r"((b)[0]),"r"((b)[1]))

// ---------------- split helpers ----------------
__device__ __forceinline__ void split2(float x, __nv_bfloat16& a0, __nv_bfloat16& a1) {
    a0 = __float2bfloat16_rn(x);
    a1 = __float2bfloat16_rn(x - __bfloat162float(a0));
}

// ---------------- kernel: split W into 2 bf16 planes ----------------
__global__ __launch_bounds__(256) void split_w(const float* __restrict__ Wa) {
    size_t base = ((size_t)blockIdx.x * 256 + threadIdx.x) * 4;
    float4 x = *reinterpret_cast<const float4*>(Wa + base);
    float v4[4] = {x.x, x.y, x.z, x.w};
    __nv_bfloat16 s0[4], s1[4];
    #pragma unroll
    for (int i = 0; i < 4; i++) split2(v4[i], s0[i], s1[i]);
    #pragma unroll
    for (int i = 0; i < 2; i++) {
        reinterpret_cast<__nv_bfloat162*>(g_W0 + base)[i] = __nv_bfloat162(s0[2*i], s0[2*i+1]);
        reinterpret_cast<__nv_bfloat162*>(g_W1 + base)[i] = __nv_bfloat162(s1[2*i], s1[2*i+1]);
    }
}

// ---------------- kernel: gather rows + split ----------------
__global__ __launch_bounds__(256) void gather_split_a(const float* __restrict__ inp,
                                                      const float* __restrict__ hc,
                                                      const int* __restrict__ slen) {
    int row = blockIdx.x;
    const float* src;
    if (row < MROWS) {
        int b = row >> 6, w = row & 63;
        src = inp + ((size_t)b * SS + (slen[b] - WW + w)) * HH;
    } else {
        src = hc + (size_t)(row - MROWS) * HH;
    }
    int i = threadIdx.x * 4;
    float4 x = *reinterpret_cast<const float4*>(src + i);
    float v4[4] = {x.x, x.y, x.z, x.w};
    __nv_bfloat16 s0[4], s1[4];
    #pragma unroll
    for (int k = 0; k < 4; k++) split2(v4[k], s0[k], s1[k]);
    size_t base = (size_t)row * HH + i;
    #pragma unroll
    for (int k = 0; k < 2; k++) {
        reinterpret_cast<__nv_bfloat162*>(g_A0 + base)[k] = __nv_bfloat162(s0[2*k], s0[2*k+1]);
        reinterpret_cast<__nv_bfloat162*>(g_A1 + base)[k] = __nv_bfloat162(s1[2*k], s1[2*k+1]);
    }
}

// ---------------- HMMA GEMM: emulated fp32 via 3 bf16 products ----------------
// (a0+a1)(b0+b1) ~= a0b0 + a0b1 + a1b0  (a1b1 ~ 2^-18 rel, dropped)
// Single __syncthreads per K-iter:
//   wait(fill(it)) ; sync ; issue fill(it+1) ; compute(stage it&1)
// The sync both publishes fill(it) and guarantees everyone finished reading
// the buffer fill(it+1) overwrites (read two iterations ago).
__global__ __launch_bounds__(256, 2) void gemm_hmma(int mode, int arow_base, int kofs,
                                                    const float* __restrict__ vv,
                                                    const float* __restrict__ ba) {
    extern __shared__ __align__(128) char smem_raw[];
    const uint32_t sbase = smem_u32(smem_raw);
    __shared__ float srow[2][BM];

    const int tid = threadIdx.x;
    const int lane = tid & 31;
    const int wid = tid >> 5;
    const int wm = (wid & 3) * 32;     // warp M offset
    const int wn = (wid >> 2) * 64;    // warp N offset
    const int n0 = blockIdx.x * BN;    // x = n-tile (A reuse in L2)
    const int m0 = blockIdx.y * BM;

    // ---- precomputed fill pointers (only +k0 varies per iter) ----
    const int rowq = tid >> 2, ch = tid & 3;
    const __nv_bfloat16* srcA[4];
    const __nv_bfloat16* srcB[4];
    uint32_t dofA[4], dofB[4];
    {
        size_t ra0 = (size_t)(arow_base + m0 + rowq) * HH + ch * 8;
        size_t ra1 = (size_t)(arow_base + m0 + 64 + rowq) * HH + ch * 8;
        srcA[0] = g_A0 + ra0;  srcA[1] = g_A0 + ra1;
        srcA[2] = g_A1 + ra0;  srcA[3] = g_A1 + ra1;
        dofA[0] = rowq * RSTRIDE + ch * 16;
        dofA[1] = (64 + rowq) * RSTRIDE + ch * 16;
        dofA[2] = SPLIT_BYTES + dofA[0];
        dofA[3] = SPLIT_BYTES + dofA[1];
        size_t rb0 = (size_t)(n0 + rowq) * (2 * HH) + kofs + ch * 8;
        size_t rb1 = (size_t)(n0 + 64 + rowq) * (2 * HH) + kofs + ch * 8;
        srcB[0] = g_W0 + rb0;  srcB[1] = g_W0 + rb1;
        srcB[2] = g_W1 + rb0;  srcB[3] = g_W1 + rb1;
        dofB[0] = B_OFF + rowq * RSTRIDE + ch * 16;
        dofB[1] = B_OFF + (64 + rowq) * RSTRIDE + ch * 16;
        dofB[2] = SPLIT_BYTES + dofB[0];
        dofB[3] = SPLIT_BYTES + dofB[1];
    }

    auto fill = [&](int s, int k0) {
        uint32_t stg = sbase + s * STAGE_BYTES;
        #pragma unroll
        for (int j = 0; j < 4; j++) cpasync16(stg + dofA[j], srcA[j] + k0);
        #pragma unroll
        for (int j = 0; j < 4; j++) cpasync16(stg + dofB[j], srcB[j] + k0);
    };

    float acc[2][8][4] = {};
    // ---- hoisted per-stage LDSM base addresses ----
    const uint32_t lrow = lane & 15;
    const uint32_t lkb = (lane >> 4) * 16;
    const uint32_t aA0 = sbase + (wm + lrow) * RSTRIDE + lkb;
    const uint32_t bA0 = sbase + B_OFF + (wn + lrow) * RSTRIDE + lkb;

    fill(0, 0);
    cp_commit();

    for (int it = 0; it < KITERS; ++it) {
        cp_wait<0>();          // fill(it) complete (only group outstanding)
        __syncthreads();       // publish fill(it); all warps done reading other stage
        if (it + 1 < KITERS) {
            fill((it + 1) & 1, (it + 1) * BK);
            cp_commit();
        }

        const uint32_t soff = (uint32_t)(it & 1) * STAGE_BYTES;
        const uint32_t aAddr = aA0 + soff;
        const uint32_t bAddr = bA0 + soff;

        #pragma unroll
        for (int ks = 0; ks < 2; ks++) {
            uint32_t a0f[2][4], a1f[2][4];
            #pragma unroll
            for (int mi = 0; mi < 2; mi++)
                LDSM(a0f[mi][0], a0f[mi][1], a0f[mi][2], a0f[mi][3],
                     aAddr + ks * 32 + mi * 16 * RSTRIDE);
            #pragma unroll
            for (int mi = 0; mi < 2; mi++)
                LDSM(a1f[mi][0], a1f[mi][1], a1f[mi][2], a1f[mi][3],
                     aAddr + SPLIT_BYTES + ks * 32 + mi * 16 * RSTRIDE);
            #pragma unroll
            for (int n2 = 0; n2 < 4; n2++) {
                uint32_t t0, t1, t2, t3;
                LDSM(t0, t1, t2, t3, bAddr + ks * 32 + n2 * 16 * RSTRIDE);
                {
                    uint32_t be[2] = {t0, t2}, bo[2] = {t1, t3};
                    #pragma unroll
                    for (int mi = 0; mi < 2; mi++) {
                        MMA(acc[mi][2*n2],   a0f[mi], be);
                        MMA(acc[mi][2*n2+1], a0f[mi], bo);
                        MMA(acc[mi][2*n2],   a1f[mi], be);
                        MMA(acc[mi][2*n2+1], a1f[mi], bo);
                    }
                }
                LDSM(t0, t1, t2, t3, bAddr + SPLIT_BYTES + ks * 32 + n2 * 16 * RSTRIDE);
                {
                    uint32_t be[2] = {t0, t2}, bo[2] = {t1, t3};
                    #pragma unroll
                    for (int mi = 0; mi < 2; mi++) {
                        MMA(acc[mi][2*n2],   a0f[mi], be);
                        MMA(acc[mi][2*n2+1], a0f[mi], bo);
                    }
                }
            }
        }
    }

    const int quad = lane >> 2, qt = lane & 3;

    if (mode == 1) {
        // epilogue: s_row = sum_n v[n]*tanh(E + u[b,n]); per-warp rows all in one batch
        const int b_warp = (m0 + wm) >> 6;
        const float* up = g_u + (size_t)b_warp * HH + n0 + wn;
        const float* vp = vv + n0 + wn;
        float rs[4] = {0.f, 0.f, 0.f, 0.f};
        #pragma unroll
        for (int mi = 0; mi < 2; mi++)
            #pragma unroll
            for (int ni = 0; ni < 8; ni++)
                #pragma unroll
                for (int r = 0; r < 4; r++) {
                    int col = ni * 8 + qt * 2 + (r & 1);
                    float e = acc[mi][ni][r] + __ldg(up + col);
                    rs[mi * 2 + (r >> 1)] += __ldg(vp + col) * tanhf(e);
                }
        #pragma unroll
        for (int i = 0; i < 4; i++) {
            rs[i] += __shfl_xor_sync(0xffffffffu, rs[i], 1);
            rs[i] += __shfl_xor_sync(0xffffffffu, rs[i], 2);
        }
        __syncthreads();   // accs drained; safe to reuse nothing, just ordering for srow
        if (qt == 0) {
            #pragma unroll
            for (int mi = 0; mi < 2; mi++)
                #pragma unroll
                for (int hf = 0; hf < 2; hf++)
                    srow[wid >> 2][wm + mi * 16 + hf * 8 + quad] = rs[mi * 2 + hf];
        }
        __syncthreads();
        if (tid < BM)
            g_part[blockIdx.x * MROWS + m0 + tid] = srow[0][tid] + srow[1][tid];
    } else {
        // u = D + b_attn
        #pragma unroll
        for (int mi = 0; mi < 2; mi++)
            #pragma unroll
            for (int ni = 0; ni < 8; ni++)
                #pragma unroll
                for (int r = 0; r < 4; r++) {
                    int row = m0 + wm + mi * 16 + (r >> 1) * 8 + quad;
                    int col = n0 + wn + ni * 8 + qt * 2 + (r & 1);
                    g_u[(size_t)row * HH + col] = acc[mi][ni][r] + __ldg(ba + col);
                }
    }
}

// ---------------- finalize: softmax + context + parent ----------------
// grid (BB, 4): block y covers 256 h-columns
__global__ __launch_bounds__(256) void finalize(const float* __restrict__ inp,
                                                const int* __restrict__ slen,
                                                const int* __restrict__ parent,
                                                float* __restrict__ out) {
    const int b = blockIdx.x;
    const int h0 = blockIdx.y * 256;
    const int tid = threadIdx.x;
    __shared__ float ssc[WW];
    __shared__ float sattn[WW];
    const int len = slen[b];

    if (tid < WW) {
        float s = 0.f;
        #pragma unroll
        for (int t = 0; t < NT; t++) s += g_part[t * MROWS + b * WW + tid];
        ssc[tid] = s;
    }
    __syncthreads();

    float mx = -1e30f;
    #pragma unroll 8
    for (int w = 0; w < WW; w++) mx = fmaxf(mx, ssc[w]);
    float sum = 0.f;
    #pragma unroll 8
    for (int w = 0; w < WW; w++) sum += expf(ssc[w] - mx);
    float inv = 1.f / sum;

    if (tid < WW) {
        float a = expf(ssc[tid] - mx) * inv;
        if (blockIdx.y == 0) out[b * WW + tid] = a;
        sattn[tid] = a;
    }
    __syncthreads();

    const float* base = inp + (size_t)b * SS * HH;
    const int off0 = (len - WW) * HH;
    {
        int h = h0 + tid;
        float acc = 0.f;
        #pragma unroll 8
        for (int w = 0; w < WW; w++)
            acc = fmaf(sattn[w], base[off0 + w * HH + h], acc);
        out[MROWS + b * HH + h] = acc;
        const int poff = (len - parent[b] - 1) * HH;
        out[MROWS + BB * HH + b * HH + h] = base[poff + h];
    }
}

// ---------------------------------------------------------------------------
extern "C" void kernel_launch(void* const* d_in, const int* in_sizes, int n_in,
                              void* d_out, int out_size) {
    const float* inp    = (const float*)d_in[0];
    const float* hc     = (const float*)d_in[1];
    const float* Wa     = (const float*)d_in[2];
    const float* ba     = (const float*)d_in[3];
    const float* v      = (const float*)d_in[4];
    const int*   slen   = (const int*)d_in[5];
    const int*   parent = (const int*)d_in[6];
    float* out = (float*)d_out;

    static int configured = 0;
    if (!configured) {
        cudaFuncSetAttribute(gemm_hmma, cudaFuncAttributeMaxDynamicSharedMemorySize, SMEM_ALLOC);
        configured = 1;
    }

    split_w<<<(HH * 2 * HH) / 1024, 256>>>(Wa);
    gather_split_a<<<AROWS, 256>>>(inp, hc, slen);
    gemm_hmma<<<dim3(NT, BB / BM), 256, SMEM_ALLOC>>>(0, MROWS, 0, v, ba);   // u
    gemm_hmma<<<dim3(NT, MROWS / BM), 256, SMEM_ALLOC>>>(1, 0, HH, v, ba);   // scores
    finalize<<<dim3(BB, 4), 256>>>(inp, slen, parent, out);
}

// round 7
// speedup vs baseline: 4.6935x; 1.1058x over previous
#include <cuda_runtime.h>
#include <cuda_bf16.h>
#include <math.h>
#include <stdint.h>

#define BB 256
#define SS 512
#define HH 1024
#define WW 64
#define MROWS (BB*WW)        // 16384 score rows
#define AROWS (MROWS + BB)   // + 256 hc rows
#define NT 8                 // N tiles of 128
#define BM 128
#define BN 128
#define BK 32                // bf16 K per stage (per plane)
#define KITERS (HH/BK)       // 32
// plane-interleaved rows: [plane0 32bf16 | plane1 32bf16] = 128B, SW128 swizzle
#define B_OFF (BM*128)                 // 16384
#define STAGE_BYTES (2*BM*128)         // 32768 (A tile + B tile)
#define NSTAGE 3
#define SMEM_ALLOC (NSTAGE*STAGE_BYTES) // 98304

// ---------------- scratch ----------------
__device__ __nv_bfloat16 g_A0[(size_t)AROWS*HH];
__device__ __nv_bfloat16 g_A1[(size_t)AROWS*HH];
__device__ __nv_bfloat16 g_W0[(size_t)HH*2*HH];
__device__ __nv_bfloat16 g_W1[(size_t)HH*2*HH];
__device__ float g_u[(size_t)BB*HH];
__device__ float g_part[NT*MROWS];

// ---------------- PTX helpers (no sm_103a-gated features) ----------------
__device__ __forceinline__ uint32_t smem_u32(const void* p) {
    uint32_t a;
    asm("{ .reg .u64 t; cvta.to.shared.u64 t, %1; cvt.u32.u64 %0, t; }" : "=r"(a) : "l"(p));
    return a;
}
__device__ __forceinline__ void cpasync16(uint32_t dst, const void* src) {
    asm volatile("cp.async.cg.shared.global [%0], [%1], 16;" :: "r"(dst), "l"(src) : "memory");
}
__device__ __forceinline__ void cp_commit() { asm volatile("cp.async.commit_group;" ::: "memory"); }
template <int N> __device__ __forceinline__ void cp_wait() {
    asm volatile("cp.async.wait_group %0;" :: "n"(N) : "memory");
}
#define LDSM(r0,r1,r2,r3,addr) \
    asm volatile("ldmatrix.sync.aligned.m8n8.x4.shared.b16 {%0,%1,%2,%3}, [%4];" \
        : "=r"(r0),"=r"(r1),"=r"(r2),"=r"(r3) : "r"(addr))
#define MMA(d, a, b) \
    asm volatile("mma.sync.aligned.m16n8k16.row.col.f32.bf16.bf16.f32 " \
        "{%0,%1,%2,%3},{%4,%5,%6,%7},{%8,%9},{%0,%1,%2,%3};" \
        : "+f"((d)[0]),"+f"((d)[1]),"+f"((d)[2]),"+f"((d)[3]) \
        : "r"((a)[0]),"r"((a)[1]),"r"((a)[2]),"r"((a)[3]),"r"((b)[0]),"r"((b)[1]))

// ---------------- split helpers ----------------
__device__ __forceinline__ void split2(float x, __nv_bfloat16& a0, __nv_bfloat16& a1) {
    a0 = __float2bfloat16_rn(x);
    a1 = __float2bfloat16_rn(x - __bfloat162float(a0));
}

// ---------------- kernel: split W into 2 bf16 planes ----------------
__global__ __launch_bounds__(256) void split_w(const float* __restrict__ Wa) {
    size_t base = ((size_t)blockIdx.x * 256 + threadIdx.x) * 4;
    float4 x = *reinterpret_cast<const float4*>(Wa + base);
    float v4[4] = {x.x, x.y, x.z, x.w};
    __nv_bfloat16 s0[4], s1[4];
    #pragma unroll
    for (int i = 0; i < 4; i++) split2(v4[i], s0[i], s1[i]);
    #pragma unroll
    for (int i = 0; i < 2; i++) {
        reinterpret_cast<__nv_bfloat162*>(g_W0 + base)[i] = __nv_bfloat162(s0[2*i], s0[2*i+1]);
        reinterpret_cast<__nv_bfloat162*>(g_W1 + base)[i] = __nv_bfloat162(s1[2*i], s1[2*i+1]);
    }
}

// ---------------- kernel: gather rows + split ----------------
__global__ __launch_bounds__(256) void gather_split_a(const float* __restrict__ inp,
                                                      const float* __restrict__ hc,
                                                      const int* __restrict__ slen) {
    int row = blockIdx.x;
    const float* src;
    if (row < MROWS) {
        int b = row >> 6, w = row & 63;
        src = inp + ((size_t)b * SS + (slen[b] - WW + w)) * HH;
    } else {
        src = hc + (size_t)(row - MROWS) * HH;
    }
    int i = threadIdx.x * 4;
    float4 x = *reinterpret_cast<const float4*>(src + i);
    float v4[4] = {x.x, x.y, x.z, x.w};
    __nv_bfloat16 s0[4], s1[4];
    #pragma unroll
    for (int k = 0; k < 4; k++) split2(v4[k], s0[k], s1[k]);
    size_t base = (size_t)row * HH + i;
    #pragma unroll
    for (int k = 0; k < 2; k++) {
        reinterpret_cast<__nv_bfloat162*>(g_A0 + base)[k] = __nv_bfloat162(s0[2*k], s0[2*k+1]);
        reinterpret_cast<__nv_bfloat162*>(g_A1 + base)[k] = __nv_bfloat162(s1[2*k], s1[2*k+1]);
    }
}

// ---------------- HMMA GEMM: emulated fp32 via 3 bf16 products ----------------
// (a0+a1)(b0+b1) ~= a0b0 + a0b1 + a1b0  (a1b1 ~ 2^-18 rel, dropped)
// 3-stage cp.async pipeline, plane-interleaved SW128 smem rows.
__global__ __launch_bounds__(256, 2) void gemm_hmma(int mode, int arow_base, int kofs,
                                                    const float* __restrict__ vv,
                                                    const float* __restrict__ ba) {
    extern __shared__ __align__(1024) char smem_raw[];
    const uint32_t sbase = smem_u32(smem_raw);
    __shared__ float srow[2][BM];

    const int tid = threadIdx.x;
    const int lane = tid & 31;
    const int wid = tid >> 5;
    const int wm = (wid & 3) * 32;     // warp M offset
    const int wn = (wid >> 2) * 64;    // warp N offset
    const int n0 = blockIdx.x * BN;    // x = n-tile (A reuse in L2)
    const int m0 = blockIdx.y * BM;

    // ---- fill assignment: 8 chunks/thread (4 A, 4 B) ----
    // chunk idx within tile: row = idx>>3, c8 = idx&7 ; p = c8>>2, kc = c8&3
    // dst = row*128 + (c8*16 ^ ((row&7)<<4))
    const __nv_bfloat16* fsrc[8];
    uint32_t fdst[8];
    {
        #pragma unroll
        for (int j = 0; j < 4; j++) {
            int idx = tid + j * 256;
            int row = idx >> 3, c8 = idx & 7, p = c8 >> 2, kc = c8 & 3;
            fsrc[j] = (p ? g_A1 : g_A0) + (size_t)(arow_base + m0 + row) * HH + kc * 8;
            fdst[j] = row * 128 + ((c8 * 16) ^ ((row & 7) << 4));
        }
        #pragma unroll
        for (int j = 0; j < 4; j++) {
            int idx = tid + j * 256;
            int row = idx >> 3, c8 = idx & 7, p = c8 >> 2, kc = c8 & 3;
            fsrc[j + 4] = (p ? g_W1 : g_W0) + (size_t)(n0 + row) * (2 * HH) + kofs + kc * 8;
            fdst[j + 4] = B_OFF + row * 128 + ((c8 * 16) ^ ((row & 7) << 4));
        }
    }

    auto fill = [&](int s, int k0) {
        uint32_t stg = sbase + s * STAGE_BYTES;
        #pragma unroll
        for (int j = 0; j < 8; j++) cpasync16(stg + fdst[j], fsrc[j] + k0);
    };

    float acc[2][8][4] = {};
    // ---- LDSM base addresses + swizzled column constants ----
    const uint32_t lrow = lane & 15;
    const uint32_t hi16 = (lane >> 4) * 16;
    const uint32_t swm = (lrow & 7) << 4;
    // csw[p][ks] = (p*64 + ks*32 + hi16) ^ swm
    uint32_t csw[2][2];
    #pragma unroll
    for (int p = 0; p < 2; p++)
        #pragma unroll
        for (int ks = 0; ks < 2; ks++)
            csw[p][ks] = ((uint32_t)(p * 64 + ks * 32) + hi16) ^ swm;
    const uint32_t aBase = sbase + (wm + lrow) * 128;
    const uint32_t bBase = sbase + B_OFF + (wn + lrow) * 128;

    fill(0, 0);
    cp_commit();
    fill(1, BK);
    cp_commit();

    uint32_t soff = 0;
    for (int it = 0; it < KITERS; ++it) {
        if (it + 1 < KITERS) cp_wait<1>(); else cp_wait<0>();
        __syncthreads();                     // publish fill(it); stage (it+2)%3 free
        if (it + 2 < KITERS) {
            fill((it + 2) % NSTAGE, (it + 2) * BK);
            cp_commit();
        }

        const uint32_t aAddr = aBase + soff;
        const uint32_t bAddr = bBase + soff;

        #pragma unroll
        for (int ks = 0; ks < 2; ks++) {
            uint32_t a0f[2][4], a1f[2][4];
            #pragma unroll
            for (int mi = 0; mi < 2; mi++)
                LDSM(a0f[mi][0], a0f[mi][1], a0f[mi][2], a0f[mi][3],
                     aAddr + mi * 2048 + csw[0][ks]);
            #pragma unroll
            for (int mi = 0; mi < 2; mi++)
                LDSM(a1f[mi][0], a1f[mi][1], a1f[mi][2], a1f[mi][3],
                     aAddr + mi * 2048 + csw[1][ks]);
            #pragma unroll
            for (int n2 = 0; n2 < 4; n2++) {
                uint32_t t0, t1, t2, t3;
                LDSM(t0, t1, t2, t3, bAddr + n2 * 2048 + csw[0][ks]);
                {
                    uint32_t be[2] = {t0, t2}, bo[2] = {t1, t3};
                    #pragma unroll
                    for (int mi = 0; mi < 2; mi++) {
                        MMA(acc[mi][2*n2],   a0f[mi], be);
                        MMA(acc[mi][2*n2+1], a0f[mi], bo);
                        MMA(acc[mi][2*n2],   a1f[mi], be);
                        MMA(acc[mi][2*n2+1], a1f[mi], bo);
                    }
                }
                LDSM(t0, t1, t2, t3, bAddr + n2 * 2048 + csw[1][ks]);
                {
                    uint32_t be[2] = {t0, t2}, bo[2] = {t1, t3};
                    #pragma unroll
                    for (int mi = 0; mi < 2; mi++) {
                        MMA(acc[mi][2*n2],   a0f[mi], be);
                        MMA(acc[mi][2*n2+1], a0f[mi], bo);
                    }
                }
            }
        }
        soff = (soff == (NSTAGE - 1) * STAGE_BYTES) ? 0 : soff + STAGE_BYTES;
    }

    const int quad = lane >> 2, qt = lane & 3;

    if (mode == 1) {
        // epilogue: s_row = sum_n v[n]*tanh(E + u[b,n]); per-warp rows all in one batch
        const int b_warp = (m0 + wm) >> 6;
        const float* up = g_u + (size_t)b_warp * HH + n0 + wn;
        const float* vp = vv + n0 + wn;
        float rs[4] = {0.f, 0.f, 0.f, 0.f};
        #pragma unroll
        for (int mi = 0; mi < 2; mi++)
            #pragma unroll
            for (int ni = 0; ni < 8; ni++)
                #pragma unroll
                for (int r = 0; r < 4; r++) {
                    int col = ni * 8 + qt * 2 + (r & 1);
                    float e = acc[mi][ni][r] + __ldg(up + col);
                    rs[mi * 2 + (r >> 1)] += __ldg(vp + col) * tanhf(e);
                }
        #pragma unroll
        for (int i = 0; i < 4; i++) {
            rs[i] += __shfl_xor_sync(0xffffffffu, rs[i], 1);
            rs[i] += __shfl_xor_sync(0xffffffffu, rs[i], 2);
        }
        __syncthreads();
        if (qt == 0) {
            #pragma unroll
            for (int mi = 0; mi < 2; mi++)
                #pragma unroll
                for (int hf = 0; hf < 2; hf++)
                    srow[wid >> 2][wm + mi * 16 + hf * 8 + quad] = rs[mi * 2 + hf];
        }
        __syncthreads();
        if (tid < BM)
            g_part[blockIdx.x * MROWS + m0 + tid] = srow[0][tid] + srow[1][tid];
    } else {
        // u = D + b_attn
        #pragma unroll
        for (int mi = 0; mi < 2; mi++)
            #pragma unroll
            for (int ni = 0; ni < 8; ni++)
                #pragma unroll
                for (int r = 0; r < 4; r++) {
                    int row = m0 + wm + mi * 16 + (r >> 1) * 8 + quad;
                    int col = n0 + wn + ni * 8 + qt * 2 + (r & 1);
                    g_u[(size_t)row * HH + col] = acc[mi][ni][r] + __ldg(ba + col);
                }
    }
}

// ---------------- finalize: softmax + context + parent ----------------
// grid (BB, 4): block y covers 256 h-columns
__global__ __launch_bounds__(256) void finalize(const float* __restrict__ inp,
                                                const int* __restrict__ slen,
                                                const int* __restrict__ parent,
                                                float* __restrict__ out) {
    const int b = blockIdx.x;
    const int h0 = blockIdx.y * 256;
    const int tid = threadIdx.x;
    __shared__ float ssc[WW];
    __shared__ float sattn[WW];
    const int len = slen[b];

    if (tid < WW) {
        float s = 0.f;
        #pragma unroll
        for (int t = 0; t < NT; t++) s += g_part[t * MROWS + b * WW + tid];
        ssc[tid] = s;
    }
    __syncthreads();

    float mx = -1e30f;
    #pragma unroll 8
    for (int w = 0; w < WW; w++) mx = fmaxf(mx, ssc[w]);
    float sum = 0.f;
    #pragma unroll 8
    for (int w = 0; w < WW; w++) sum += expf(ssc[w] - mx);
    float inv = 1.f / sum;

    if (tid < WW) {
        float a = expf(ssc[tid] - mx) * inv;
        if (blockIdx.y == 0) out[b * WW + tid] = a;
        sattn[tid] = a;
    }
    __syncthreads();

    const float* base = inp + (size_t)b * SS * HH;
    const int off0 = (len - WW) * HH;
    {
        int h = h0 + tid;
        float acc = 0.f;
        #pragma unroll 8
        for (int w = 0; w < WW; w++)
            acc = fmaf(sattn[w], base[off0 + w * HH + h], acc);
        out[MROWS + b * HH + h] = acc;
        const int poff = (len - parent[b] - 1) * HH;
        out[MROWS + BB * HH + b * HH + h] = base[poff + h];
    }
}

// ---------------------------------------------------------------------------
extern "C" void kernel_launch(void* const* d_in, const int* in_sizes, int n_in,
                              void* d_out, int out_size) {
    const float* inp    = (const float*)d_in[0];
    const float* hc     = (const float*)d_in[1];
    const float* Wa     = (const float*)d_in[2];
    const float* ba     = (const float*)d_in[3];
    const float* v      = (const float*)d_in[4];
    const int*   slen   = (const int*)d_in[5];
    const int*   parent = (const int*)d_in[6];
    float* out = (float*)d_out;

    static int configured = 0;
    if (!configured) {
        cudaFuncSetAttribute(gemm_hmma, cudaFuncAttributeMaxDynamicSharedMemorySize, SMEM_ALLOC);
        configured = 1;
    }

    split_w<<<(HH * 2 * HH) / 1024, 256>>>(Wa);
    gather_split_a<<<AROWS, 256>>>(inp, hc, slen);
    gemm_hmma<<<dim3(NT, BB / BM), 256, SMEM_ALLOC>>>(0, MROWS, 0, v, ba);   // u
    gemm_hmma<<<dim3(NT, MROWS / BM), 256, SMEM_ALLOC>>>(1, 0, HH, v, ba);   // scores
    finalize<<<dim3(BB, 4), 256>>>(inp, slen, parent, out);
}